// round 8
// baseline (speedup 1.0000x reference)
#include <cuda_runtime.h>
#include <math.h>

#define BB 16
#define MM 60
#define TT 80
#define NA 128
#define NL 64
#define NP 20
#define NLP (NL*NP)        // 1280
#define NTHR 896           // 28 warps: 20 scan + 8 jerk
#define SPB 8              // slices (blocks) per batch
#define NSTG 64            // staged lane points
#define BIGF 3.4e38f

__device__ float g_partial[BB*MM];
__device__ int   g_sync[BB];        // zero-init; selector resets each launch

__global__ __launch_bounds__(NTHR) void fused_kernel(
    const float* __restrict__ mode_logits,
    const float* __restrict__ all_trajs,
    const float* __restrict__ agents_now,
    const float* __restrict__ agents_mask,
    const float* __restrict__ map_lanes,
    const float* __restrict__ lanes_mask,
    float* __restrict__ out,
    int write_idx)
{
    __shared__ __align__(16) float2 s_ln[NSTG];   // first 64 lane points, pre-masked
    __shared__ int  s_cc[8], s_uc[8];
    __shared__ int  s_last, s_sel;

    const int blk  = blockIdx.x;
    const int b    = blk >> 3;                    // batch
    const int s    = blk & 7;                     // slice
    const int MPB  = (s < 4) ? 8 : 7;             // modes in this slice
    const int m0   = (s < 4) ? s*8 : 32 + (s-4)*7;
    const int NDT  = MPB * TT;                    // 560 or 640 tasks
    const int tid  = threadIdx.x;
    const int w    = tid >> 5;
    const int lane = tid & 31;

    if (tid < 8){ s_cc[tid] = 0; s_uc[tid] = 0; }

    const float* trajb = all_trajs + (size_t)b * MM * TT * 3;

    // ── Ego prefetch (overlaps with staging)
    float ex = 0.0f, ey = 0.0f;
    if (tid < NDT){
        const float* p = trajb + (size_t)(m0*TT + tid)*3;   // (m0+tid/TT, tid%TT)
        ex = p[0]; ey = p[1];
    }

    // ── Stage ONLY the first 64 lane points (witness almost surely inside);
    //    invalid lane -> 1e18 (can never satisfy d2<=9, == +BIG semantics)
    if (tid < NSTG){
        float valid = lanes_mask[b*NL + tid/NP];
        const float* src = map_lanes + ((size_t)b*NLP + tid)*3;
        float x = src[0], y = src[1];
        if (valid == 0.0f){ x = 1e18f; y = 0.0f; }
        s_ln[tid] = make_float2(x, y);
    }
    __syncthreads();

    float js = 0.0f;                          // jerk warp partial
    if (tid < NDT){
        const int ml = tid / TT;              // local mode

        // ── Agents: scan global directly, 4 agents (5×LDG.128) per chunk.
        //    Classification identical to reference: valid && d2 < 4.
        bool coll = false;
        {
            const float4* agp = (const float4*)(agents_now + (size_t)b*NA*4);
            const float4* agm = (const float4*)(agents_mask + (size_t)b*NA);
            #pragma unroll 1
            for (int c = 0; c < NA/4; c++){
                float4 mk = agm[c];
                float4 p0 = agp[c*4+0], p1 = agp[c*4+1];
                float4 p2 = agp[c*4+2], p3 = agp[c*4+3];
                float dx0 = ex-p0.x, dy0 = ey-p0.y;
                float dx1 = ex-p1.x, dy1 = ey-p1.y;
                float dx2 = ex-p2.x, dy2 = ey-p2.y;
                float dx3 = ex-p3.x, dy3 = ey-p3.y;
                bool ok = (mk.x != 0.0f && fmaf(dx0,dx0,dy0*dy0) < 4.0f)
                       || (mk.y != 0.0f && fmaf(dx1,dx1,dy1*dy1) < 4.0f)
                       || (mk.z != 0.0f && fmaf(dx2,dx2,dy2*dy2) < 4.0f)
                       || (mk.w != 0.0f && fmaf(dx3,dx3,dy3*dy3) < 4.0f);
                if (ok){ coll = true; break; }
            }
        }

        // ── Lanes: fast path over 64 staged points (8 per chunk) ...
        bool near = false;
        {
            const float4* pl = (const float4*)s_ln;   // 2 points per float4
            #pragma unroll 1
            for (int c = 0; c < NSTG/2; c += 4){
                float n0 = BIGF, n1 = BIGF;
                #pragma unroll
                for (int k = 0; k < 4; k++){
                    float4 p = pl[c+k];
                    float dxa = ex-p.x, dya = ey-p.y;
                    float dxb = ex-p.z, dyb = ey-p.w;
                    n0 = fminf(n0, fmaf(dxa,dxa,dya*dya));
                    n1 = fminf(n1, fmaf(dxb,dxb,dyb*dyb));
                }
                if (fminf(n0, n1) <= 9.0f){ near = true; break; }
            }
            // ... exact global fallback for points 64..1279 (statistically never)
            if (!near){
                #pragma unroll 1
                for (int j = NSTG; j < NLP && !near; j += 8){
                    bool hit = false;
                    #pragma unroll
                    for (int k = 0; k < 8; k++){
                        int jj = j + k;
                        float mv = lanes_mask[b*NL + jj/NP];
                        const float* q = map_lanes + ((size_t)b*NLP + jj)*3;
                        float dx = ex - q[0], dy = ey - q[1];
                        if (mv != 0.0f && fmaf(dx,dx,dy*dy) <= 9.0f) hit = true;
                    }
                    if (hit) near = true;
                }
            }
        }

        if (coll)  atomicAdd(&s_cc[ml], 1);   // integer -> deterministic
        if (!near) atomicAdd(&s_uc[ml], 1);
    }
    else if (w >= 20 && w < 20 + MPB){
        // ── Jerk sums, overlapped with the scans (global-only)
        const int m = m0 + (w - 20);
        for (int t = lane; t < TT-3; t += 32){
            const float* tr = trajb + (size_t)(m*TT + t)*3;
            float jx = tr[9]  - 3.0f*tr[6] + 3.0f*tr[3] - tr[0];
            float jy = tr[10] - 3.0f*tr[7] + 3.0f*tr[4] - tr[1];
            js += sqrtf(jx*jx + jy*jy);
        }
        #pragma unroll
        for (int d = 16; d; d >>= 1) js += __shfl_xor_sync(0xffffffffu, js, d);
    }
    __syncthreads();

    // ── Publish partial scores for this slice
    if (w >= 20 && w < 20 + MPB && lane == 0){
        const int ml = w - 20;
        const int m  = m0 + ml;
        float comfort   = -js / (float)(TT-3);
        float progress  = trajb[(size_t)(m*TT + TT-1)*3];
        float collision = -(float)s_cc[ml] / (float)TT;
        float drivable  = -(float)s_uc[ml] / (float)TT;
        g_partial[b*MM + m] = 0.1f*comfort + 0.5f*progress
                            + 1.0f*collision + 0.3f*drivable;
        __threadfence();                      // release before counter bump
    }
    __syncthreads();

    // ── Per-batch handshake: 8th arriving slice selects
    if (tid == 0){
        int c = atomicAdd(&g_sync[b], 1);
        s_last = (c == SPB-1);
    }
    __syncthreads();
    if (!s_last) return;
    __threadfence();                          // acquire other slices' partials

    // ── Selection (warp 0): softmax + first-max argmax
    if (tid < 32){
        float l0 = mode_logits[b*MM + lane];                                  // m = lane
        float l1 = (lane < MM-32) ? mode_logits[b*MM + 32 + lane] : -BIGF;    // m = lane+32

        float mx = fmaxf(l0, l1);
        #pragma unroll
        for (int d = 16; d; d >>= 1) mx = fmaxf(mx, __shfl_xor_sync(0xffffffffu, mx, d));

        float e0 = __expf(l0 - mx);
        float e1 = (lane < MM-32) ? __expf(l1 - mx) : 0.0f;
        float sum = e0 + e1;
        #pragma unroll
        for (int d = 16; d; d >>= 1) sum += __shfl_xor_sync(0xffffffffu, sum, d);
        sum = __shfl_sync(0xffffffffu, sum, 0);

        float sc0 = e0/sum + g_partial[b*MM + lane];
        float sc1 = (lane < MM-32) ? e1/sum + g_partial[b*MM + 32 + lane] : -BIGF;

        float bs; int bi;
        if (sc1 > sc0){ bs = sc1; bi = lane + 32; } else { bs = sc0; bi = lane; }
        #pragma unroll
        for (int d = 16; d; d >>= 1){
            float ov = __shfl_xor_sync(0xffffffffu, bs, d);
            int   oi = __shfl_xor_sync(0xffffffffu, bi, d);
            if (ov > bs || (ov == bs && oi < bi)){ bs = ov; bi = oi; }
        }
        if (lane == 0) s_sel = bi;            // first-max (jnp.argmax tie-break)
    }
    __syncthreads();

    // ── Emit selected trajectory (+ index), reset counter for graph replay
    const int sel = s_sel;
    const float* src = trajb + (size_t)(sel*TT)*3;
    if (tid < TT*3) out[b*TT*3 + tid] = src[tid];
    if (tid == 0){
        if (write_idx) out[BB*TT*3 + b] = (float)sel;
        g_sync[b] = 0;
    }
}

extern "C" void kernel_launch(void* const* d_in, const int* in_sizes, int n_in,
                              void* d_out, int out_size)
{
    const float* mode_logits    = (const float*)d_in[0];
    const float* all_trajs      = (const float*)d_in[1];
    const float* agents_now     = (const float*)d_in[2];
    const float* agents_mask    = (const float*)d_in[3];
    const float* map_lanes      = (const float*)d_in[4];
    const float* map_lanes_mask = (const float*)d_in[5];
    float* out = (float*)d_out;

    int write_idx = (out_size >= BB*TT*3 + BB) ? 1 : 0;

    fused_kernel<<<BB*SPB, NTHR>>>(mode_logits, all_trajs, agents_now, agents_mask,
                                   map_lanes, map_lanes_mask, out, write_idx);
}

// round 9
// speedup vs baseline: 1.7642x; 1.7642x over previous
#include <cuda_runtime.h>
#include <math.h>

#define BB 16
#define MM 60
#define TT 80
#define NA 128
#define NL 64
#define NP 20
#define NLP (NL*NP)        // 1280
#define NTHR 896           // 28 warps: 20 scan + 8 jerk
#define SPB 8              // slices (blocks) per batch
#define NSTG 256           // staged lane points (witness ~certainly inside)
#define BIGF 3.4e38f

__device__ float g_partial[BB*MM];
__device__ int   g_sync[BB];        // zero-init; selector resets each launch

__global__ __launch_bounds__(NTHR) void fused_kernel(
    const float* __restrict__ mode_logits,
    const float* __restrict__ all_trajs,
    const float* __restrict__ agents_now,
    const float* __restrict__ agents_mask,
    const float* __restrict__ map_lanes,
    const float* __restrict__ lanes_mask,
    float* __restrict__ out,
    int write_idx)
{
    __shared__ __align__(16) float2 s_ag[NA];     // 1 KB, fully staged
    __shared__ __align__(16) float2 s_ln[NSTG];   // 2 KB, first 256 pts pre-masked
    __shared__ int  s_cc[8], s_uc[8];
    __shared__ int  s_last, s_sel;

    const int blk  = blockIdx.x;
    const int b    = blk >> 3;                    // batch
    const int s    = blk & 7;                     // slice
    const int MPB  = (s < 4) ? 8 : 7;             // modes in this slice
    const int m0   = (s < 4) ? s*8 : 32 + (s-4)*7;
    const int NDT  = MPB * TT;                    // 560 or 640 tasks
    const int tid  = threadIdx.x;
    const int w    = tid >> 5;
    const int lane = tid & 31;

    if (tid < 8){ s_cc[tid] = 0; s_uc[tid] = 0; }

    const float* trajb = all_trajs + (size_t)b * MM * TT * 3;

    // ── Ego prefetch (overlaps with staging latency)
    float ex = 0.0f, ey = 0.0f;
    if (tid < NDT){
        const float* p = trajb + (size_t)(m0*TT + tid)*3;
        ex = p[0]; ey = p[1];
    }

    // ── Stage agents; invalid -> far away (== +BIG penalty semantics)
    if (tid < NA){
        float valid = agents_mask[b*NA + tid];
        float ax = agents_now[(b*NA + tid)*4 + 0];
        float ay = agents_now[(b*NA + tid)*4 + 1];
        if (valid == 0.0f){ ax = 1e18f; ay = 0.0f; }
        s_ag[tid] = make_float2(ax, ay);
    }
    // ── Stage first NSTG lane points (mask repeats per point)
    if (tid < NSTG){
        float valid = lanes_mask[b*NL + tid/NP];
        const float* src = map_lanes + ((size_t)b*NLP + tid)*3;
        float x = src[0], y = src[1];
        if (valid == 0.0f){ x = 1e18f; y = 0.0f; }
        s_ln[tid] = make_float2(x, y);
    }
    __syncthreads();

    const float4* pa = (const float4*)s_ag;   // 2 points per float4
    const float4* pl = (const float4*)s_ln;

    // ── Warps 0..19: distance tasks (one per thread).
    //    Warps 20..27: jerk sums, fully overlapped (global-only).
    float js = 0.0f;                          // jerk warp partial
    if (tid < NDT){
        const int ml = tid / TT;              // local mode

        bool coll = false;   // exists agent with d2 < 4       (min_dist < 2)
        bool near = false;   // exists lane point with d2 <= 9 (min_lane <= 3)

        float a0 = BIGF, a1 = BIGF;
        #pragma unroll 1
        for (int c = 0; c < NA/2; c += 4){    // 8 points per chunk, from shared
            #pragma unroll
            for (int k = 0; k < 4; k++){
                float4 p = pa[c+k];
                float dx0 = ex - p.x, dy0 = ey - p.y;
                float dx1 = ex - p.z, dy1 = ey - p.w;
                a0 = fminf(a0, fmaf(dx0, dx0, dy0*dy0));
                a1 = fminf(a1, fmaf(dx1, dx1, dy1*dy1));
            }
            if (fminf(a0, a1) < 4.0f){ coll = true; break; }
        }

        float n0 = BIGF, n1 = BIGF;
        #pragma unroll 1
        for (int c = 0; c < NSTG/2; c += 4){  // staged fast path
            #pragma unroll
            for (int k = 0; k < 4; k++){
                float4 p = pl[c+k];
                float dx0 = ex - p.x, dy0 = ey - p.y;
                float dx1 = ex - p.z, dy1 = ey - p.w;
                n0 = fminf(n0, fmaf(dx0, dx0, dy0*dy0));
                n1 = fminf(n1, fmaf(dx1, dx1, dy1*dy1));
            }
            if (fminf(n0, n1) <= 9.0f){ near = true; break; }
        }
        // exact mask-aware global fallback, points NSTG..NLP-1 (statistically never)
        if (!near){
            #pragma unroll 1
            for (int j = NSTG; j < NLP && !near; j += 8){
                bool hit = false;
                #pragma unroll
                for (int k = 0; k < 8; k++){
                    int jj = j + k;
                    float mv = lanes_mask[b*NL + jj/NP];
                    const float* q = map_lanes + ((size_t)b*NLP + jj)*3;
                    float dx = ex - q[0], dy = ey - q[1];
                    if (mv != 0.0f && fmaf(dx, dx, dy*dy) <= 9.0f) hit = true;
                }
                if (hit) near = true;
            }
        }

        if (coll)  atomicAdd(&s_cc[ml], 1);   // integer -> deterministic
        if (!near) atomicAdd(&s_uc[ml], 1);
    }
    else if (w >= 20 && w < 20 + MPB){
        const int m = m0 + (w - 20);
        for (int t = lane; t < TT-3; t += 32){
            const float* tr = trajb + (size_t)(m*TT + t)*3;
            float jx = tr[9]  - 3.0f*tr[6] + 3.0f*tr[3] - tr[0];
            float jy = tr[10] - 3.0f*tr[7] + 3.0f*tr[4] - tr[1];
            js += sqrtf(jx*jx + jy*jy);
        }
        #pragma unroll
        for (int d = 16; d; d >>= 1) js += __shfl_xor_sync(0xffffffffu, js, d);
    }
    __syncthreads();

    // ── Publish partial scores for this slice
    if (w >= 20 && w < 20 + MPB && lane == 0){
        const int ml = w - 20;
        const int m  = m0 + ml;
        float comfort   = -js / (float)(TT-3);
        float progress  = trajb[(size_t)(m*TT + TT-1)*3];
        float collision = -(float)s_cc[ml] / (float)TT;
        float drivable  = -(float)s_uc[ml] / (float)TT;
        g_partial[b*MM + m] = 0.1f*comfort + 0.5f*progress
                            + 1.0f*collision + 0.3f*drivable;
        __threadfence();                      // release before counter bump
    }
    __syncthreads();

    // ── Per-batch handshake: 8th arriving slice selects
    if (tid == 0){
        int c = atomicAdd(&g_sync[b], 1);
        s_last = (c == SPB-1);
    }
    __syncthreads();
    if (!s_last) return;
    __threadfence();                          // acquire other slices' partials

    // ── Selection (warp 0): softmax + first-max argmax
    if (tid < 32){
        float l0 = mode_logits[b*MM + lane];                                  // m = lane
        float l1 = (lane < MM-32) ? mode_logits[b*MM + 32 + lane] : -BIGF;    // m = lane+32

        float mx = fmaxf(l0, l1);
        #pragma unroll
        for (int d = 16; d; d >>= 1) mx = fmaxf(mx, __shfl_xor_sync(0xffffffffu, mx, d));

        float e0 = __expf(l0 - mx);
        float e1 = (lane < MM-32) ? __expf(l1 - mx) : 0.0f;
        float sum = e0 + e1;
        #pragma unroll
        for (int d = 16; d; d >>= 1) sum += __shfl_xor_sync(0xffffffffu, sum, d);
        sum = __shfl_sync(0xffffffffu, sum, 0);

        float sc0 = e0/sum + g_partial[b*MM + lane];
        float sc1 = (lane < MM-32) ? e1/sum + g_partial[b*MM + 32 + lane] : -BIGF;

        float bs; int bi;
        if (sc1 > sc0){ bs = sc1; bi = lane + 32; } else { bs = sc0; bi = lane; }
        #pragma unroll
        for (int d = 16; d; d >>= 1){
            float ov = __shfl_xor_sync(0xffffffffu, bs, d);
            int   oi = __shfl_xor_sync(0xffffffffu, bi, d);
            if (ov > bs || (ov == bs && oi < bi)){ bs = ov; bi = oi; }
        }
        if (lane == 0) s_sel = bi;            // first-max (jnp.argmax tie-break)
    }
    __syncthreads();

    // ── Emit selected trajectory (+ index), reset counter for graph replay
    const int sel = s_sel;
    const float* src = trajb + (size_t)(sel*TT)*3;
    if (tid < TT*3) out[b*TT*3 + tid] = src[tid];
    if (tid == 0){
        if (write_idx) out[BB*TT*3 + b] = (float)sel;
        g_sync[b] = 0;
    }
}

extern "C" void kernel_launch(void* const* d_in, const int* in_sizes, int n_in,
                              void* d_out, int out_size)
{
    const float* mode_logits    = (const float*)d_in[0];
    const float* all_trajs      = (const float*)d_in[1];
    const float* agents_now     = (const float*)d_in[2];
    const float* agents_mask    = (const float*)d_in[3];
    const float* map_lanes      = (const float*)d_in[4];
    const float* map_lanes_mask = (const float*)d_in[5];
    float* out = (float*)d_out;

    int write_idx = (out_size >= BB*TT*3 + BB) ? 1 : 0;

    fused_kernel<<<BB*SPB, NTHR>>>(mode_logits, all_trajs, agents_now, agents_mask,
                                   map_lanes, map_lanes_mask, out, write_idx);
}